// round 11
// baseline (speedup 1.0000x reference)
#include <cuda_runtime.h>

// KVCacheHeadAttention: B=32, E=4096 -> D=128, MAX_TOKENS=2048.
// Prefix-softmax: out[b,s,:] = sum_{t<=s} e_t*v[b,t,:] / sum_{t<=s} e_t.
// R10: qkv rebuilt as transposed-W smem GEMM (4b x 4d register tile,
// 1 LDS.128 + 4 broadcast LDS.32 per 16 FMA, conflict-free) -> fixes the
// LDS-bound 11.9us qkv. Scan front-loads all global reads so DRAM latency
// hides under the base/prefix computation.

#define BB 32
#define DD 128
#define D4 32
#define EE 4096
#define MAXT 2048
#define CHUNK 128
#define SUB 32
#define MAXSUB 64
#define NSPLIT 64        // 64 e-splits of 64
#define EC 64            // e-chunk per qkv block

__device__ float g_part[3][NSPLIT][BB][DD];  // qkv split-K partials
__device__ float g_e[BB][MAXT];              // exp(scores)
__device__ float g_cnum[BB][MAXSUB][DD];     // 32-token numerator partials
__device__ float g_cden[BB][MAXSUB];         // 32-token denominator partials

__device__ __forceinline__ float4 f4add(float4 a, float4 b) {
    return make_float4(a.x+b.x, a.y+b.y, a.z+b.z, a.w+b.w);
}
__device__ __forceinline__ float4 f4fma(float s, float4 v, float4 a) {
    return make_float4(fmaf(s,v.x,a.x), fmaf(s,v.y,a.y),
                       fmaf(s,v.z,a.z), fmaf(s,v.w,a.w));
}
__device__ __forceinline__ float4 f4scale(float4 v, float s) {
    return make_float4(v.x*s, v.y*s, v.z*s, v.w*s);
}

// ---------- K1: QKV split-K partials (192 blocks = 3m x 64esp, 256 thr) ---
// Tile: all 32 b x all 128 d, e-chunk 64. W staged TRANSPOSED wt[e][d] so
// compute reads are 1 conflict-free LDS.128 + 4 smem broadcasts per 16 FMA.
__global__ __launch_bounds__(256) void qkv_part_kernel(
    const float* __restrict__ x,  const float* __restrict__ Wq,
    const float* __restrict__ Wk, const float* __restrict__ Wv) {
    __shared__ float xs[32][EC + 4];        // [b][e]   8.7 KB
    __shared__ float wt[EC][DD + 4];        // [e][d]  33.8 KB
    int m   = blockIdx.x;                   // 0..2
    int esp = blockIdx.y;                   // 0..63
    const float* W = (m == 0) ? Wq : ((m == 1) ? Wk : Wv);
    int e0  = esp * EC;
    int tid = threadIdx.x;

    // x tile: 32 rows x 64 e = 512 float4, 2 per thread
    for (int i = tid; i < 32 * (EC / 4); i += 256) {
        int r = i >> 4;
        int j = (i & 15) << 2;
        *(float4*)&xs[r][j] = *(const float4*)(x + (size_t)r * EE + e0 + j);
    }
    // W tile transposed: thread d_l=tid&127 streams one 128B line of its row
    {
        int d_l = tid & 127;
        int eg  = (tid >> 7) * 32;          // 0 or 32
        const float* wrow = W + (size_t)d_l * EE + e0 + eg;
        #pragma unroll
        for (int k = 0; k < 8; k++) {
            float4 wv = __ldcs((const float4*)(wrow + k * 4));
            wt[eg + k*4 + 0][d_l] = wv.x;
            wt[eg + k*4 + 1][d_l] = wv.y;
            wt[eg + k*4 + 2][d_l] = wv.z;
            wt[eg + k*4 + 3][d_l] = wv.w;
        }
    }
    __syncthreads();

    int ti = tid >> 5;      // 0..7  -> b rows ti*4..ti*4+3
    int tj = tid & 31;      // 0..31 -> d cols tj*4..tj*4+3
    float acc[4][4];
    #pragma unroll
    for (int i = 0; i < 4; i++)
        #pragma unroll
        for (int j = 0; j < 4; j++) acc[i][j] = 0.0f;

    #pragma unroll 8
    for (int e = 0; e < EC; e++) {
        float4 wv = *(float4*)&wt[e][tj * 4];
        #pragma unroll
        for (int i = 0; i < 4; i++) {
            float xi = xs[ti * 4 + i][e];
            acc[i][0] = fmaf(xi, wv.x, acc[i][0]);
            acc[i][1] = fmaf(xi, wv.y, acc[i][1]);
            acc[i][2] = fmaf(xi, wv.z, acc[i][2]);
            acc[i][3] = fmaf(xi, wv.w, acc[i][3]);
        }
    }
    #pragma unroll
    for (int i = 0; i < 4; i++)
        *(float4*)&g_part[m][esp][ti * 4 + i][tj * 4] =
            make_float4(acc[i][0], acc[i][1], acc[i][2], acc[i][3]);
}

// -------- K2: score + 32-token chunk partials (grid nchunks x B) ---------
__global__ __launch_bounds__(512) void score_kernel(
    const float* __restrict__ kv, const int* __restrict__ np, int max_k) {
    int b = blockIdx.y, c = blockIdx.x, tid = threadIdx.x;
    __shared__ float qs[DD], kn[DD], es[CHUNK];
    __shared__ float4 vns4[D4];
    __shared__ float4 red[4][4][D4];

    // prologue: reduce split-K partials (96 threads, float4 over 64 splits)
    if (tid < 96) {
        int m  = tid >> 5;
        int dd = tid & 31;
        float4 acc = make_float4(0.f, 0.f, 0.f, 0.f);
        #pragma unroll 16
        for (int e = 0; e < NSPLIT; e++)
            acc = f4add(acc, *((const float4*)&g_part[m][e][b][0] + dd));
        if (m == 0)      *((float4*)qs + dd) = acc;
        else if (m == 1) *((float4*)kn + dd) = acc;
        else             vns4[dd] = acc;
    }
    __syncthreads();

    int npos = np[b];
    int t0   = c * CHUNK;

    // scores: 4 lanes per token, streaming K loads
    {
        int tok = tid >> 2, qq = tid & 3;
        int t   = t0 + tok;
        float sdot = 0.0f;
        int d0 = qq * 32;
        if (t == npos) {
            #pragma unroll
            for (int d = 0; d < 32; d++) sdot += qs[d0 + d] * kn[d0 + d];
        } else {
            const float4* krow = (const float4*)(kv + ((size_t)b * MAXT + t) * DD) + qq * 8;
            #pragma unroll
            for (int d = 0; d < 8; d++) {
                float4 kk = __ldcs(krow + d);
                sdot += qs[d0+4*d]*kk.x + qs[d0+4*d+1]*kk.y
                      + qs[d0+4*d+2]*kk.z + qs[d0+4*d+3]*kk.w;
            }
        }
        sdot += __shfl_xor_sync(0xffffffffu, sdot, 1);
        sdot += __shfl_xor_sync(0xffffffffu, sdot, 2);
        float e = (t < max_k) ? expf(sdot * 0.08838834764831845f) : 0.0f;
        if (qq == 0) {
            es[tok]   = e;
            g_e[b][t] = e;
        }
    }
    __syncthreads();

    // 32-token denominators (warps 0..3)
    if (tid < 128) {
        float de = es[tid];
        #pragma unroll
        for (int o = 16; o; o >>= 1) de += __shfl_xor_sync(0xffffffffu, de, o);
        if ((tid & 31) == 0) g_cden[b][c * 4 + (tid >> 5)] = de;
    }

    // numerator partials: thread = (sc, tq, d4), 8 LDG.128 each
    int sc = tid >> 7;
    int tq = (tid >> 5) & 3;
    int d4 = tid & 31;
    int tb = t0 + sc * SUB + tq * 8;
    const float4* vbase = (const float4*)(kv + (size_t)BB * MAXT * DD
                                          + ((size_t)b * MAXT + tb) * DD) + d4;
    float4 acc = make_float4(0.f, 0.f, 0.f, 0.f);
    #pragma unroll
    for (int u = 0; u < 8; u++) {
        float4 vv = vbase[(size_t)u * D4];
        if (tb + u == npos) vv = vns4[d4];
        acc = f4fma(es[sc * SUB + tq * 8 + u], vv, acc);
    }
    red[sc][tq][d4] = acc;
    __syncthreads();
    if (tid < 128) {
        int sc2 = tid >> 5, dd = tid & 31;
        float4 s0 = f4add(f4add(red[sc2][0][dd], red[sc2][1][dd]),
                          f4add(red[sc2][2][dd], red[sc2][3][dd]));
        *((float4*)&g_cnum[b][c * 4 + sc2][0] + dd) = s0;
    }
}

// --------- K3: prefix scan + output, all global reads front-loaded -------
__global__ __launch_bounds__(512) void scan_kernel(
    const float* __restrict__ kv, const int* __restrict__ np,
    float* __restrict__ out, int max_k) {
    int b = blockIdx.y, c = blockIdx.x, tid = threadIdx.x;
    __shared__ float es[CHUNK], rden[CHUNK];
    __shared__ float4 vns4[D4];
    __shared__ float4 bred[16][D4];
    __shared__ float4 part[16][D4];
    __shared__ float warp_sums[4];
    __shared__ float denbase_s;

    int t0 = c * CHUNK;
    int s  = tid >> 5;       // 0..15
    int d4 = tid & 31;
    int tb = t0 + s * 8;

    // ---- front-load ALL global reads (latency overlaps later compute) ----
    const float4* vbase = (const float4*)(kv + (size_t)BB * MAXT * DD
                                          + ((size_t)b * MAXT + tb) * DD) + d4;
    float4 vv[8];
    #pragma unroll
    for (int u = 0; u < 8; u++) vv[u] = vbase[(size_t)u * D4];   // in-bounds < MAXT
    int npos = np[b];
    if (tid < CHUNK) es[tid] = g_e[b][t0 + tid];
    if (s == 15) {                        // warp 15: reduce v-new partials
        float4 acc = make_float4(0.f, 0.f, 0.f, 0.f);
        #pragma unroll 16
        for (int e = 0; e < NSPLIT; e++)
            acc = f4add(acc, *((const float4*)&g_part[2][e][b][0] + d4));
        vns4[d4] = acc;
    }
    // chunk numerator base: rows i < 4c, 16-slice stride
    {
        float4 acc = make_float4(0.f, 0.f, 0.f, 0.f);
        int nrow = 4 * c;
        for (int i = s; i < nrow; i += 16)
            acc = f4add(acc, *((const float4*)&g_cnum[b][i][0] + d4));
        bred[s][d4] = acc;
    }
    // denominator base: warp 0
    if (tid < 32) {
        float db = 0.0f;
        int nrow = 4 * c;
        for (int i = tid; i < nrow; i += 32) db += g_cden[b][i];
        #pragma unroll
        for (int o = 16; o; o >>= 1) db += __shfl_xor_sync(0xffffffffu, db, o);
        if (tid == 0) denbase_s = db;
    }
    __syncthreads();

    // base tree reduce
    #pragma unroll
    for (int off = 8; off; off >>= 1) {
        if (s < off) bred[s][d4] = f4add(bred[s][d4], bred[s + off][d4]);
        __syncthreads();
    }

    // denominator prefixes over 128 tokens
    float dv = 0.0f;
    if (tid < 128) {
        dv = es[tid];
        int lane = tid & 31;
        #pragma unroll
        for (int o = 1; o < 32; o <<= 1) {
            float n = __shfl_up_sync(0xffffffffu, dv, o);
            if (lane >= o) dv += n;
        }
        if (lane == 31) warp_sums[tid >> 5] = dv;
    }
    __syncthreads();
    if (tid < 128) {
        int w = tid >> 5;
        float wb = denbase_s;
        for (int i = 0; i < w; i++) wb += warp_sums[i];
        rden[tid] = 1.0f / (wb + dv);
    }

    // npos substitution (vns4 visible since first barrier) + 8-token partial
    float4 vn = vns4[d4];
    float4 psum = make_float4(0.f, 0.f, 0.f, 0.f);
    #pragma unroll
    for (int u = 0; u < 8; u++) {
        if (tb + u == npos) vv[u] = vn;
        psum = f4fma(es[s * 8 + u], vv[u], psum);
    }
    part[s][d4] = psum;
    __syncthreads();

    float4 acc = bred[0][d4];
    for (int j = 0; j < s; j++) acc = f4add(acc, part[j][d4]);

    // scan + streaming stores
    float4* obase = (float4*)(out + ((size_t)b * max_k + tb) * DD) + d4;
    #pragma unroll
    for (int u = 0; u < 8; u++) {
        acc = f4fma(es[s * 8 + u], vv[u], acc);
        if (tb + u < max_k)
            __stcs(obase + (size_t)u * D4, f4scale(acc, rden[s * 8 + u]));
    }
}

// ----------------------------------------------------------------- launch
extern "C" void kernel_launch(void* const* d_in, const int* in_sizes, int n_in,
                              void* d_out, int out_size) {
    const float* x   = (const float*)d_in[0];
    const float* Wq  = (const float*)d_in[1];
    const float* Wk  = (const float*)d_in[2];
    const float* Wv  = (const float*)d_in[3];
    const float* kvc = (const float*)d_in[4];
    const int*   np  = (const int*)d_in[5];
    float* out = (float*)d_out;

    int max_k   = out_size / (BB * DD);
    int nchunks = (max_k + CHUNK - 1) / CHUNK;   // 12 for max_k=1536

    qkv_part_kernel<<<dim3(3, NSPLIT), 256>>>(x, Wq, Wk, Wv);
    score_kernel<<<dim3(nchunks, BB), 512>>>(kvc, np, max_k);
    scan_kernel<<<dim3(nchunks, BB), 512>>>(kvc, np, out, max_k);
}

// round 12
// speedup vs baseline: 1.1871x; 1.1871x over previous
#include <cuda_runtime.h>

// KVCacheHeadAttention: B=32, E=4096 -> D=128, MAX_TOKENS=2048.
// Prefix-softmax: out[b,s,:] = sum_{t<=s} e_t*v[b,t,:] / sum_{t<=s} e_t.
// R12: atomic QKV with NO zero kernel. __device__ globals start zeroed at
// module load; the LAST kernel (scan) re-zeroes g_qkv[.][b] after its final
// use (per-b done counter, increment-after-use -> no spin, no race), so
// every graph replay starts clean. Consumers read q/k/v directly (no
// split-reduce prologues). qkv grid 768 blocks for occupancy.

#define BB 32
#define DD 128
#define D4 32
#define EE 4096
#define MAXT 2048
#define CHUNK 128
#define SUB 32
#define MAXSUB 64
#define ECH 64            // e-chunk per qkv block

__device__ float g_qkv[3][BB][DD];           // q,k,v (atomic-accumulated)
__device__ float g_e[BB][MAXT];              // exp(scores)
__device__ float g_cnum[BB][MAXSUB][DD];     // 32-token numerator partials
__device__ float g_cden[BB][MAXSUB];         // 32-token denominator partials
__device__ int   g_doneb[BB];                // per-b scan-finished counters

__device__ __forceinline__ float4 f4add(float4 a, float4 b) {
    return make_float4(a.x+b.x, a.y+b.y, a.z+b.z, a.w+b.w);
}
__device__ __forceinline__ float4 f4fma(float s, float4 v, float4 a) {
    return make_float4(fmaf(s,v.x,a.x), fmaf(s,v.y,a.y),
                       fmaf(s,v.z,a.z), fmaf(s,v.w,a.w));
}
__device__ __forceinline__ float4 f4scale(float4 v, float s) {
    return make_float4(v.x*s, v.y*s, v.z*s, v.w*s);
}

// -------- K1: QKV GEMM, atomic accumulate (grid (12,64), 256 thr) --------
// blockIdx.x = m*4+dtile, blockIdx.y = esplit (64-wide). 32b x 32d tile,
// 2x2 per thread, atomicAdd into g_qkv (zero at entry by contract).
__global__ __launch_bounds__(256) void qkv_kernel(
    const float* __restrict__ x,  const float* __restrict__ Wq,
    const float* __restrict__ Wk, const float* __restrict__ Wv) {
    __shared__ float xs[32][ECH + 4];
    __shared__ float ws[32][ECH + 4];
    int m   = blockIdx.x >> 2;
    int dt  = blockIdx.x & 3;
    int e0  = blockIdx.y * ECH;
    const float* W = (m == 0) ? Wq : ((m == 1) ? Wk : Wv);
    int tid = threadIdx.x;

    // 32 rows x 64 floats per tile = 512 float4 per array, 2 per thread
    for (int i = tid; i < 32 * (ECH / 4); i += 256) {
        int r = i >> 4;
        int j = (i & 15) << 2;
        *(float4*)&xs[r][j] = *(const float4*)(x + (size_t)r * EE + e0 + j);
        *(float4*)&ws[r][j] = __ldcs((const float4*)(W + (size_t)(dt * 32 + r) * EE + e0 + j));
    }
    __syncthreads();

    int ti = tid & 15, tj = tid >> 4;  // b-pair {ti,ti+16}, d-pair {tj,tj+16}
    float a00 = 0.f, a01 = 0.f, a10 = 0.f, a11 = 0.f;
    #pragma unroll
    for (int e = 0; e < ECH; e += 4) {
        float4 xa = *(float4*)&xs[ti][e];
        float4 xb = *(float4*)&xs[ti + 16][e];
        float4 wa = *(float4*)&ws[tj][e];
        float4 wb = *(float4*)&ws[tj + 16][e];
        a00 += xa.x*wa.x + xa.y*wa.y + xa.z*wa.z + xa.w*wa.w;
        a01 += xa.x*wb.x + xa.y*wb.y + xa.z*wb.z + xa.w*wb.w;
        a10 += xb.x*wa.x + xb.y*wa.y + xb.z*wa.z + xb.w*wa.w;
        a11 += xb.x*wb.x + xb.y*wb.y + xb.z*wb.z + xb.w*wb.w;
    }
    atomicAdd(&g_qkv[m][ti][dt * 32 + tj],           a00);
    atomicAdd(&g_qkv[m][ti][dt * 32 + tj + 16],      a01);
    atomicAdd(&g_qkv[m][ti + 16][dt * 32 + tj],      a10);
    atomicAdd(&g_qkv[m][ti + 16][dt * 32 + tj + 16], a11);
}

// -------- K2: score + 32-token chunk partials (grid nchunks x B) ---------
__global__ __launch_bounds__(512) void score_kernel(
    const float* __restrict__ kv, const int* __restrict__ np, int max_k) {
    int b = blockIdx.y, c = blockIdx.x, tid = threadIdx.x;
    __shared__ float qs[DD], kn[DD], es[CHUNK];
    __shared__ float4 vns4[D4];
    __shared__ float4 red[4][4][D4];

    // direct q/k/v loads (L2-hot, 3x128 floats)
    if (tid < 128) {
        qs[tid] = g_qkv[0][b][tid];
        kn[tid] = g_qkv[1][b][tid];
    } else if (tid < 160) {
        vns4[tid - 128] = *((const float4*)&g_qkv[2][b][0] + (tid - 128));
    }
    __syncthreads();

    int npos = np[b];
    int t0   = c * CHUNK;

    // scores: 4 lanes per token, streaming K loads
    {
        int tok = tid >> 2, qq = tid & 3;
        int t   = t0 + tok;
        float sdot = 0.0f;
        int d0 = qq * 32;
        if (t == npos) {
            #pragma unroll
            for (int d = 0; d < 32; d++) sdot += qs[d0 + d] * kn[d0 + d];
        } else {
            const float4* krow = (const float4*)(kv + ((size_t)b * MAXT + t) * DD) + qq * 8;
            #pragma unroll
            for (int d = 0; d < 8; d++) {
                float4 kk = __ldcs(krow + d);
                sdot += qs[d0+4*d]*kk.x + qs[d0+4*d+1]*kk.y
                      + qs[d0+4*d+2]*kk.z + qs[d0+4*d+3]*kk.w;
            }
        }
        sdot += __shfl_xor_sync(0xffffffffu, sdot, 1);
        sdot += __shfl_xor_sync(0xffffffffu, sdot, 2);
        float e = (t < max_k) ? expf(sdot * 0.08838834764831845f) : 0.0f;
        if (qq == 0) {
            es[tok]   = e;
            g_e[b][t] = e;
        }
    }
    __syncthreads();

    // 32-token denominators (warps 0..3)
    if (tid < 128) {
        float de = es[tid];
        #pragma unroll
        for (int o = 16; o; o >>= 1) de += __shfl_xor_sync(0xffffffffu, de, o);
        if ((tid & 31) == 0) g_cden[b][c * 4 + (tid >> 5)] = de;
    }

    // numerator partials: thread = (sc, tq, d4), 8 LDG.128 each
    int sc = tid >> 7;
    int tq = (tid >> 5) & 3;
    int d4 = tid & 31;
    int tb = t0 + sc * SUB + tq * 8;
    const float4* vbase = (const float4*)(kv + (size_t)BB * MAXT * DD
                                          + ((size_t)b * MAXT + tb) * DD) + d4;
    float4 acc = make_float4(0.f, 0.f, 0.f, 0.f);
    #pragma unroll
    for (int u = 0; u < 8; u++) {
        float4 vv = vbase[(size_t)u * D4];
        if (tb + u == npos) vv = vns4[d4];
        acc = f4fma(es[sc * SUB + tq * 8 + u], vv, acc);
    }
    red[sc][tq][d4] = acc;
    __syncthreads();
    if (tid < 128) {
        int sc2 = tid >> 5, dd = tid & 31;
        float4 s0 = f4add(f4add(red[sc2][0][dd], red[sc2][1][dd]),
                          f4add(red[sc2][2][dd], red[sc2][3][dd]));
        *((float4*)&g_cnum[b][c * 4 + sc2][0] + dd) = s0;
    }
}

// --------- K3: prefix scan + output + self-clean (grid nchunks x B) ------
__global__ __launch_bounds__(512) void scan_kernel(
    const float* __restrict__ kv, const int* __restrict__ np,
    float* __restrict__ out, int max_k) {
    int b = blockIdx.y, c = blockIdx.x, tid = threadIdx.x;
    __shared__ float es[CHUNK], rden[CHUNK];
    __shared__ float4 vns4[D4];
    __shared__ float4 bred[16][D4];
    __shared__ float4 part[16][D4];
    __shared__ float warp_sums[4];
    __shared__ float denbase_s;
    __shared__ int   lastflag;

    int t0 = c * CHUNK;
    int s  = tid >> 5;       // 0..15
    int d4 = tid & 31;
    int tb = t0 + s * 8;

    // ---- front-load all global reads ----
    const float4* vbase = (const float4*)(kv + (size_t)BB * MAXT * DD
                                          + ((size_t)b * MAXT + tb) * DD) + d4;
    float4 vv[8];
    #pragma unroll
    for (int u = 0; u < 8; u++) vv[u] = vbase[(size_t)u * D4];   // in-bounds < MAXT
    int npos = np[b];
    if (tid < CHUNK) es[tid] = g_e[b][t0 + tid];
    if (tid >= 480) vns4[tid - 480] = *((const float4*)&g_qkv[2][b][0] + (tid - 480));

    // chunk numerator base: rows i < 4c, 16-slice stride
    {
        float4 acc = make_float4(0.f, 0.f, 0.f, 0.f);
        int nrow = 4 * c;
        for (int i = s; i < nrow; i += 16)
            acc = f4add(acc, *((const float4*)&g_cnum[b][i][0] + d4));
        bred[s][d4] = acc;
    }
    // denominator base: warp 0
    if (tid < 32) {
        float db = 0.0f;
        int nrow = 4 * c;
        for (int i = tid; i < nrow; i += 32) db += g_cden[b][i];
        #pragma unroll
        for (int o = 16; o; o >>= 1) db += __shfl_xor_sync(0xffffffffu, db, o);
        if (tid == 0) denbase_s = db;
    }
    __syncthreads();

    // base tree reduce
    #pragma unroll
    for (int off = 8; off; off >>= 1) {
        if (s < off) bred[s][d4] = f4add(bred[s][d4], bred[s + off][d4]);
        __syncthreads();
    }

    // denominator prefixes over 128 tokens
    float dv = 0.0f;
    if (tid < 128) {
        dv = es[tid];
        int lane = tid & 31;
        #pragma unroll
        for (int o = 1; o < 32; o <<= 1) {
            float n = __shfl_up_sync(0xffffffffu, dv, o);
            if (lane >= o) dv += n;
        }
        if (lane == 31) warp_sums[tid >> 5] = dv;
    }
    __syncthreads();
    if (tid < 128) {
        int w = tid >> 5;
        float wb = denbase_s;
        for (int i = 0; i < w; i++) wb += warp_sums[i];
        rden[tid] = 1.0f / (wb + dv);
    }

    // npos substitution + 8-token partial
    float4 vn = vns4[d4];
    float4 psum = make_float4(0.f, 0.f, 0.f, 0.f);
    #pragma unroll
    for (int u = 0; u < 8; u++) {
        if (tb + u == npos) vv[u] = vn;
        psum = f4fma(es[s * 8 + u], vv[u], psum);
    }
    part[s][d4] = psum;
    __syncthreads();

    float4 acc = bred[0][d4];
    for (int j = 0; j < s; j++) acc = f4add(acc, part[j][d4]);

    // scan + streaming stores
    float4* obase = (float4*)(out + ((size_t)b * max_k + tb) * DD) + d4;
    #pragma unroll
    for (int u = 0; u < 8; u++) {
        acc = f4fma(es[s * 8 + u], vv[u], acc);
        if (tb + u < max_k)
            __stcs(obase + (size_t)u * D4, f4scale(acc, rden[s * 8 + u]));
    }

    // ---- self-clean g_qkv[.][b] for next replay (increment-after-use) ----
    __syncthreads();                 // all reads of g_qkv/vns done block-wide
    if (tid == 0)
        lastflag = (atomicAdd(&g_doneb[b], 1) == (int)gridDim.x - 1);
    __syncthreads();
    if (lastflag) {                  // only runs when all 12 blocks of b done
        if (tid < 3 * DD) g_qkv[tid >> 7][b][tid & 127] = 0.0f;
        if (tid == 0)     g_doneb[b] = 0;
    }
}

// ----------------------------------------------------------------- launch
extern "C" void kernel_launch(void* const* d_in, const int* in_sizes, int n_in,
                              void* d_out, int out_size) {
    const float* x   = (const float*)d_in[0];
    const float* Wq  = (const float*)d_in[1];
    const float* Wk  = (const float*)d_in[2];
    const float* Wv  = (const float*)d_in[3];
    const float* kvc = (const float*)d_in[4];
    const int*   np  = (const int*)d_in[5];
    float* out = (float*)d_out;

    int max_k   = out_size / (BB * DD);
    int nchunks = (max_k + CHUNK - 1) / CHUNK;   // 12 for max_k=1536

    qkv_kernel<<<dim3(12, 64), 256>>>(x, Wq, Wk, Wv);
    score_kernel<<<dim3(nchunks, BB), 512>>>(kvc, np, max_k);
    scan_kernel<<<dim3(nchunks, BB), 512>>>(kvc, np, out, max_k);
}

// round 13
// speedup vs baseline: 1.2075x; 1.0172x over previous
#include <cuda_runtime.h>

// KVCacheHeadAttention: B=32, E=4096 -> D=128, MAX_TOKENS=2048.
// Prefix-softmax: out[b,s,:] = sum_{t<=s} e_t*v[b,t,:] / sum_{t<=s} e_t.
// R13: R2's proven qkv geometry (ECH=128, grid(12,32), 2x2 tile, atomics)
// + R12's self-cleaning state (no zero kernel: scan re-zeroes g_qkv[.][b]
// after last use via per-b done counter; __device__ globals are zero at
// module load, so correctness run and every graph replay start clean).

#define BB 32
#define DD 128
#define D4 32
#define EE 4096
#define MAXT 2048
#define CHUNK 128
#define SUB 32
#define MAXSUB 64
#define ECH 128           // e-chunk per qkv block (R2 geometry)

__device__ float g_qkv[3][BB][DD];           // q,k,v (atomic-accumulated)
__device__ float g_e[BB][MAXT];              // exp(scores)
__device__ float g_cnum[BB][MAXSUB][DD];     // 32-token numerator partials
__device__ float g_cden[BB][MAXSUB];         // 32-token denominator partials
__device__ int   g_doneb[BB];                // per-b scan-finished counters

__device__ __forceinline__ float4 f4add(float4 a, float4 b) {
    return make_float4(a.x+b.x, a.y+b.y, a.z+b.z, a.w+b.w);
}
__device__ __forceinline__ float4 f4fma(float s, float4 v, float4 a) {
    return make_float4(fmaf(s,v.x,a.x), fmaf(s,v.y,a.y),
                       fmaf(s,v.z,a.z), fmaf(s,v.w,a.w));
}
__device__ __forceinline__ float4 f4scale(float4 v, float s) {
    return make_float4(v.x*s, v.y*s, v.z*s, v.w*s);
}

// -------- K1: QKV GEMM, atomic accumulate (grid (12,32), 256 thr) --------
// blockIdx.x = m*4+dtile, blockIdx.y = esplit (128-wide). 32b x 32d tile,
// 2x2 per thread, atomicAdd into g_qkv (zero at entry by contract).
__global__ __launch_bounds__(256) void qkv_kernel(
    const float* __restrict__ x,  const float* __restrict__ Wq,
    const float* __restrict__ Wk, const float* __restrict__ Wv) {
    __shared__ float xs[32][ECH + 4];
    __shared__ float ws[32][ECH + 4];
    int m   = blockIdx.x >> 2;
    int dt  = blockIdx.x & 3;
    int e0  = blockIdx.y * ECH;
    const float* W = (m == 0) ? Wq : ((m == 1) ? Wk : Wv);
    int tid = threadIdx.x;

    // 32 rows x 128 floats per tile = 1024 float4 per array, 4 per thread
    for (int i = tid; i < 32 * (ECH / 4); i += 256) {
        int r = i >> 5;
        int j = (i & 31) << 2;
        *(float4*)&xs[r][j] = *(const float4*)(x + (size_t)r * EE + e0 + j);
        *(float4*)&ws[r][j] = __ldcs((const float4*)(W + (size_t)(dt * 32 + r) * EE + e0 + j));
    }
    __syncthreads();

    int ti = tid & 15, tj = tid >> 4;  // b-pair {ti,ti+16}, d-pair {tj,tj+16}
    float a00 = 0.f, a01 = 0.f, a10 = 0.f, a11 = 0.f;
    #pragma unroll
    for (int e = 0; e < ECH; e += 4) {
        float4 xa = *(float4*)&xs[ti][e];
        float4 xb = *(float4*)&xs[ti + 16][e];
        float4 wa = *(float4*)&ws[tj][e];
        float4 wb = *(float4*)&ws[tj + 16][e];
        a00 += xa.x*wa.x + xa.y*wa.y + xa.z*wa.z + xa.w*wa.w;
        a01 += xa.x*wb.x + xa.y*wb.y + xa.z*wb.z + xa.w*wb.w;
        a10 += xb.x*wa.x + xb.y*wa.y + xb.z*wa.z + xb.w*wa.w;
        a11 += xb.x*wb.x + xb.y*wb.y + xb.z*wb.z + xb.w*wb.w;
    }
    atomicAdd(&g_qkv[m][ti][dt * 32 + tj],           a00);
    atomicAdd(&g_qkv[m][ti][dt * 32 + tj + 16],      a01);
    atomicAdd(&g_qkv[m][ti + 16][dt * 32 + tj],      a10);
    atomicAdd(&g_qkv[m][ti + 16][dt * 32 + tj + 16], a11);
}

// -------- K2: score + 32-token chunk partials (grid nchunks x B) ---------
__global__ __launch_bounds__(512) void score_kernel(
    const float* __restrict__ kv, const int* __restrict__ np, int max_k) {
    int b = blockIdx.y, c = blockIdx.x, tid = threadIdx.x;
    __shared__ float qs[DD], kn[DD], es[CHUNK];
    __shared__ float4 vns4[D4];
    __shared__ float4 red[4][4][D4];

    // direct q/k/v loads (L2-hot, 3x128 floats)
    if (tid < 128) {
        qs[tid] = g_qkv[0][b][tid];
        kn[tid] = g_qkv[1][b][tid];
    } else if (tid < 160) {
        vns4[tid - 128] = *((const float4*)&g_qkv[2][b][0] + (tid - 128));
    }
    __syncthreads();

    int npos = np[b];
    int t0   = c * CHUNK;

    // scores: 4 lanes per token, streaming K loads
    {
        int tok = tid >> 2, qq = tid & 3;
        int t   = t0 + tok;
        float sdot = 0.0f;
        int d0 = qq * 32;
        if (t == npos) {
            #pragma unroll
            for (int d = 0; d < 32; d++) sdot += qs[d0 + d] * kn[d0 + d];
        } else {
            const float4* krow = (const float4*)(kv + ((size_t)b * MAXT + t) * DD) + qq * 8;
            #pragma unroll
            for (int d = 0; d < 8; d++) {
                float4 kk = __ldcs(krow + d);
                sdot += qs[d0+4*d]*kk.x + qs[d0+4*d+1]*kk.y
                      + qs[d0+4*d+2]*kk.z + qs[d0+4*d+3]*kk.w;
            }
        }
        sdot += __shfl_xor_sync(0xffffffffu, sdot, 1);
        sdot += __shfl_xor_sync(0xffffffffu, sdot, 2);
        float e = (t < max_k) ? expf(sdot * 0.08838834764831845f) : 0.0f;
        if (qq == 0) {
            es[tok]   = e;
            g_e[b][t] = e;
        }
    }
    __syncthreads();

    // 32-token denominators (warps 0..3)
    if (tid < 128) {
        float de = es[tid];
        #pragma unroll
        for (int o = 16; o; o >>= 1) de += __shfl_xor_sync(0xffffffffu, de, o);
        if ((tid & 31) == 0) g_cden[b][c * 4 + (tid >> 5)] = de;
    }

    // numerator partials: thread = (sc, tq, d4), 8 LDG.128 each
    int sc = tid >> 7;
    int tq = (tid >> 5) & 3;
    int d4 = tid & 31;
    int tb = t0 + sc * SUB + tq * 8;
    const float4* vbase = (const float4*)(kv + (size_t)BB * MAXT * DD
                                          + ((size_t)b * MAXT + tb) * DD) + d4;
    float4 acc = make_float4(0.f, 0.f, 0.f, 0.f);
    #pragma unroll
    for (int u = 0; u < 8; u++) {
        float4 vv = vbase[(size_t)u * D4];
        if (tb + u == npos) vv = vns4[d4];
        acc = f4fma(es[sc * SUB + tq * 8 + u], vv, acc);
    }
    red[sc][tq][d4] = acc;
    __syncthreads();
    if (tid < 128) {
        int sc2 = tid >> 5, dd = tid & 31;
        float4 s0 = f4add(f4add(red[sc2][0][dd], red[sc2][1][dd]),
                          f4add(red[sc2][2][dd], red[sc2][3][dd]));
        *((float4*)&g_cnum[b][c * 4 + sc2][0] + dd) = s0;
    }
}

// --------- K3: prefix scan + output + self-clean (grid nchunks x B) ------
__global__ __launch_bounds__(512) void scan_kernel(
    const float* __restrict__ kv, const int* __restrict__ np,
    float* __restrict__ out, int max_k) {
    int b = blockIdx.y, c = blockIdx.x, tid = threadIdx.x;
    __shared__ float es[CHUNK], rden[CHUNK];
    __shared__ float4 vns4[D4];
    __shared__ float4 bred[16][D4];
    __shared__ float4 part[16][D4];
    __shared__ float warp_sums[4];
    __shared__ float denbase_s;
    __shared__ int   lastflag;

    int t0 = c * CHUNK;
    int s  = tid >> 5;       // 0..15
    int d4 = tid & 31;
    int tb = t0 + s * 8;

    // ---- front-load all global reads ----
    const float4* vbase = (const float4*)(kv + (size_t)BB * MAXT * DD
                                          + ((size_t)b * MAXT + tb) * DD) + d4;
    float4 vv[8];
    #pragma unroll
    for (int u = 0; u < 8; u++) vv[u] = vbase[(size_t)u * D4];   // in-bounds < MAXT
    int npos = np[b];
    if (tid < CHUNK) es[tid] = g_e[b][t0 + tid];
    if (tid >= 480) vns4[tid - 480] = *((const float4*)&g_qkv[2][b][0] + (tid - 480));

    // chunk numerator base: rows i < 4c, 16-slice stride
    {
        float4 acc = make_float4(0.f, 0.f, 0.f, 0.f);
        int nrow = 4 * c;
        for (int i = s; i < nrow; i += 16)
            acc = f4add(acc, *((const float4*)&g_cnum[b][i][0] + d4));
        bred[s][d4] = acc;
    }
    // denominator base: warp 0
    if (tid < 32) {
        float db = 0.0f;
        int nrow = 4 * c;
        for (int i = tid; i < nrow; i += 32) db += g_cden[b][i];
        #pragma unroll
        for (int o = 16; o; o >>= 1) db += __shfl_xor_sync(0xffffffffu, db, o);
        if (tid == 0) denbase_s = db;
    }
    __syncthreads();

    // base tree reduce
    #pragma unroll
    for (int off = 8; off; off >>= 1) {
        if (s < off) bred[s][d4] = f4add(bred[s][d4], bred[s + off][d4]);
        __syncthreads();
    }

    // denominator prefixes over 128 tokens
    float dv = 0.0f;
    if (tid < 128) {
        dv = es[tid];
        int lane = tid & 31;
        #pragma unroll
        for (int o = 1; o < 32; o <<= 1) {
            float n = __shfl_up_sync(0xffffffffu, dv, o);
            if (lane >= o) dv += n;
        }
        if (lane == 31) warp_sums[tid >> 5] = dv;
    }
    __syncthreads();
    if (tid < 128) {
        int w = tid >> 5;
        float wb = denbase_s;
        for (int i = 0; i < w; i++) wb += warp_sums[i];
        rden[tid] = 1.0f / (wb + dv);
    }

    // npos substitution + 8-token partial
    float4 vn = vns4[d4];
    float4 psum = make_float4(0.f, 0.f, 0.f, 0.f);
    #pragma unroll
    for (int u = 0; u < 8; u++) {
        if (tb + u == npos) vv[u] = vn;
        psum = f4fma(es[s * 8 + u], vv[u], psum);
    }
    part[s][d4] = psum;
    __syncthreads();

    float4 acc = bred[0][d4];
    for (int j = 0; j < s; j++) acc = f4add(acc, part[j][d4]);

    // scan + streaming stores
    float4* obase = (float4*)(out + ((size_t)b * max_k + tb) * DD) + d4;
    #pragma unroll
    for (int u = 0; u < 8; u++) {
        acc = f4fma(es[s * 8 + u], vv[u], acc);
        if (tb + u < max_k)
            __stcs(obase + (size_t)u * D4, f4scale(acc, rden[s * 8 + u]));
    }

    // ---- self-clean g_qkv[.][b] for next replay (increment-after-use) ----
    __syncthreads();                 // all reads of g_qkv/vns done block-wide
    if (tid == 0)
        lastflag = (atomicAdd(&g_doneb[b], 1) == (int)gridDim.x - 1);
    __syncthreads();
    if (lastflag) {                  // only runs when all 12 blocks of b done
        if (tid < 3 * DD) g_qkv[tid >> 7][b][tid & 127] = 0.0f;
        if (tid == 0)     g_doneb[b] = 0;
    }
}

// ----------------------------------------------------------------- launch
extern "C" void kernel_launch(void* const* d_in, const int* in_sizes, int n_in,
                              void* d_out, int out_size) {
    const float* x   = (const float*)d_in[0];
    const float* Wq  = (const float*)d_in[1];
    const float* Wk  = (const float*)d_in[2];
    const float* Wv  = (const float*)d_in[3];
    const float* kvc = (const float*)d_in[4];
    const int*   np  = (const int*)d_in[5];
    float* out = (float*)d_out;

    int max_k   = out_size / (BB * DD);
    int nchunks = (max_k + CHUNK - 1) / CHUNK;   // 12 for max_k=1536

    qkv_kernel<<<dim3(12, 32), 256>>>(x, Wq, Wk, Wv);
    score_kernel<<<dim3(nchunks, BB), 512>>>(kvc, np, max_k);
    scan_kernel<<<dim3(nchunks, BB), 512>>>(kvc, np, out, max_k);
}